// round 17
// baseline (speedup 1.0000x reference)
#include <cuda_runtime.h>

#define NPTS      8192
#define THREADS   256
#define WPC       8
#define R         4
#define NC        (R / 2)                // 2 packed chains
#define ICHUNK    128                    // i-points per task
#define IBLKS     (NPTS / ICHUNK)        // 64
#define JTILE     32
#define JBLKS     (NPTS / JTILE)         // 256
#define JPB       (ICHUNK / JTILE)       // 4 j-tiles per i-chunk
#define NENTRY    (3 * IBLKS)            // 192
#define GRID      592
#define PREP_CTAS 32
#define NBIN      1024
#define BPC       (NBIN / PREP_CTAS)
#define CUT       40.0f                  // drop pairs with k < 2^-40
#define EPS_SORT  0.03f                  // bin-granularity sort slack
#define LOG2E_F   1.4426950408889634f
#define FULLMASK  0xFFFFFFFFu

typedef unsigned long long ull;

__device__ __forceinline__ float ex2_approx(float x) {
    float r;
    asm("ex2.approx.ftz.f32 %0, %1;" : "=f"(r) : "f"(x));
    return r;
}
__device__ __forceinline__ ull pack2(float lo, float hi) {
    ull p;
    asm("mov.b64 %0, {%1, %2};" : "=l"(p) : "f"(lo), "f"(hi));
    return p;
}
__device__ __forceinline__ unsigned int ld_acq(unsigned int* p) {
    unsigned int v;
    asm volatile("ld.acquire.gpu.u32 %0, [%1];" : "=r"(v) : "l"(p));
    return v;
}
__device__ __forceinline__ void st_rel(unsigned int* p, unsigned int v) {
    asm volatile("st.release.gpu.global.u32 [%0], %1;" :: "l"(p), "r"(v) : "memory");
}
__device__ __forceinline__ void arrive_rel(unsigned int* p) {
    asm volatile("red.release.gpu.global.add.u32 [%0], 1;" :: "l"(p) : "memory");
}

// Scratch (no allocations allowed; zero-initialized at load, reset each run)
__device__ float2 g_sb[NPTS], g_st[NPTS];      // scaled (uncentered), x-sorted
__device__ unsigned int g_histb[NBIN], g_histt[NBIN];
__device__ unsigned int g_curb[NBIN],  g_curt[NBIN];
__device__ double g_mean[2];
__device__ float  g_delta[2];
__device__ double g_sum[3];
__device__ int    g_prefix[NENTRY + 1];
__device__ int    g_jstart[NENTRY];
__device__ unsigned int g_barB, g_barE, g_barDel;
__device__ unsigned int g_flagC;
__device__ unsigned int g_task, g_done;

__device__ __forceinline__ void block_reduce_add(double v, double* dst,
                                                 double* sred, int tid) {
    sred[tid] = v;
    __syncthreads();
    for (int s = THREADS / 2; s > 0; s >>= 1) {
        if (tid < s) sred[tid] += sred[tid + s];
        __syncthreads();
    }
    if (tid == 0) atomicAdd(dst, sred[0]);
    __syncthreads();
}
__device__ __forceinline__ void prefix1024(unsigned int* hist, unsigned int* cur,
                                           unsigned int* ps, int tid) {
    unsigned int l0 = hist[tid * 4],     l1 = hist[tid * 4 + 1];
    unsigned int l2 = hist[tid * 4 + 2], l3 = hist[tid * 4 + 3];
    unsigned int tot = l0 + l1 + l2 + l3;
    ps[tid] = tot;
    __syncthreads();
    for (int off = 1; off < THREADS; off <<= 1) {
        unsigned int v = ps[tid];
        unsigned int u = (tid >= off) ? ps[tid - off] : 0u;
        __syncthreads();
        ps[tid] = v + u;
        __syncthreads();
    }
    unsigned int excl = ps[tid] - tot;
    cur[tid * 4] = excl; excl += l0;
    cur[tid * 4 + 1] = excl; excl += l1;
    cur[tid * 4 + 2] = excl; excl += l2;
    cur[tid * 4 + 3] = excl;
    __syncthreads();
}

#define SPIN(cond) do { while (cond) { __nanosleep(32); } } while (0)

#define MINIBAR(ctr) do {                                            \
    __threadfence();                                                 \
    __syncthreads();                                                 \
    if (tid == 0) {                                                  \
        arrive_rel(&(ctr));                                          \
        SPIN(ld_acq(&(ctr)) < PREP_CTAS);                            \
    }                                                                \
    __syncthreads();                                                 \
} while (0)

// j-tile x endpoint accessors on the sorted arrays
__device__ __forceinline__ float jxm(const float2* s, int k) { return s[k * JTILE].x; }
__device__ __forceinline__ float jxM(const float2* s, int k) { return s[k * JTILE + JTILE - 1].x; }

// last k in [0,n) with jxm(k) <= V, or -1
__device__ __forceinline__ int upper_jxm(const float2* s, int n, float V) {
    int lo = -1, hi = n - 1;
    while (lo < hi) {
        int mid = (lo + hi + 1) >> 1;
        if (jxm(s, mid) <= V) lo = mid; else hi = mid - 1;
    }
    return lo;
}
// first k in [0,n) with jxM(k) >= V, or n
__device__ __forceinline__ int lower_jxM(const float2* s, int n, float V) {
    int lo = 0, hi = n;
    while (lo < hi) {
        int mid = (lo + hi) >> 1;
        if (jxM(s, mid) < V) lo = mid + 1; else hi = mid;
    }
    return lo;
}

// ---------------------------------------------------------------------------
// Kernel 1 (32 CTAs): delta reduction, 1-D x counting sort (1024 bins) of
// both scaled clouds, and the dense task table: for each (type, i-chunk of
// 128), the j-tiles (32 pts) within the x-cutoff form a CONTIGUOUS range.
// Kernel boundary = global barrier for the pair kernel (no cross-grid gates).
// ---------------------------------------------------------------------------
__global__ __launch_bounds__(THREADS) void k_prep(
        const float* __restrict__ base, const float* __restrict__ tgt,
        const float* __restrict__ log_sigma, const float* __restrict__ log_scale) {
    __shared__ double sred[THREADS];
    __shared__ unsigned int ps[THREADS];

    const int tid = threadIdx.x;
    const int cta = blockIdx.x;
    const int i   = cta * THREADS + tid;

    const float s0 = expf(log_scale[0]);
    const float s1 = expf(log_scale[1]);
    const float sigma = expf(log_sigma[0]);
    const float c2 = -(1.0f / (2.0f * sigma * sigma)) * LOG2E_F;
    const float rcut = sqrtf(CUT / (-c2)) + EPS_SORT;

    const float2 pb = ((const float2*)base)[i];
    const float2 pt = ((const float2*)tgt)[i];
    const float bx = pb.x * s0, by = pb.y * s1;
    const float tx = pt.x * s0, ty = pt.y * s1;

    // delta = cb - ct (for bt term; shift-invariance removes centering)
    block_reduce_add((double)bx - (double)tx, &g_mean[0], sred, tid);
    block_reduce_add((double)by - (double)ty, &g_mean[1], sred, tid);
    if (tid == 0) {
        __threadfence();
        unsigned int d = atomicAdd(&g_barDel, 1u);
        if (d == PREP_CTAS - 1) {
            g_delta[0] = (float)(atomicAdd(&g_mean[0], 0.0) / (double)NPTS);
            g_delta[1] = (float)(atomicAdd(&g_mean[1], 0.0) / (double)NPTS);
        }
    }

    // histogram (hist arrays are zero: load-time init / previous-run reset)
    const int binb = min(max((int)((bx + 6.4f) * 80.0f), 0), NBIN - 1);
    const int bint = min(max((int)((tx + 6.4f) * 80.0f), 0), NBIN - 1);
    atomicAdd(&g_histb[binb], 1u);
    atomicAdd(&g_histt[bint], 1u);
    MINIBAR(g_barB);

    // prefix (CTA0), others spin on flag
    if (cta == 0) {
        prefix1024(g_histb, g_curb, ps, tid);
        prefix1024(g_histt, g_curt, ps, tid);
        __threadfence();
        __syncthreads();
        if (tid == 0) st_rel(&g_flagC, 1u);
    } else {
        if (tid == 0) SPIN(ld_acq(&g_flagC) == 0u);
    }
    __syncthreads();

    // scatter
    {
        unsigned int pos = atomicAdd(&g_curb[binb], 1u);
        g_sb[pos] = make_float2(bx, by);
        pos = atomicAdd(&g_curt[bint], 1u);
        g_st[pos] = make_float2(tx, ty);
    }
    MINIBAR(g_barE);

    // table (CTA0, threads 0..191; one entry each)
    if (cta == 0) {
        __shared__ int cnt[NENTRY];
        __shared__ int js[NENTRY];
        if (tid < NENTRY) {
            const int type = tid >> 6;          // /64
            const int it   = tid & (IBLKS - 1);
            int jstart, jend;
            if (type == 0) {
                float ihi = g_sb[it * ICHUNK + ICHUNK - 1].x;
                jstart = it * JPB;
                jend = upper_jxm(g_sb, JBLKS, ihi + rcut);
            } else if (type == 1) {
                float ihi = g_st[it * ICHUNK + ICHUNK - 1].x;
                jstart = it * JPB;
                jend = upper_jxm(g_st, JBLKS, ihi + rcut);
            } else {
                float dxv = g_delta[0];
                float ilo = g_sb[it * ICHUNK].x;
                float ihi = g_sb[it * ICHUNK + ICHUNK - 1].x;
                jstart = lower_jxM(g_st, JBLKS, ilo - rcut - dxv);
                jend   = upper_jxm(g_st, JBLKS, ihi + rcut - dxv);
            }
            cnt[tid] = max(0, jend - jstart + 1);
            js[tid]  = jstart;
        }
        __syncthreads();
        if (tid == 0) {
            int acc = 0;
            for (int e = 0; e < NENTRY; e++) {
                g_prefix[e] = acc;
                g_jstart[e] = js[e];
                acc += cnt[e];
            }
            g_prefix[NENTRY] = acc;
        }
    }
}

// ---------------------------------------------------------------------------
// Kernel 2 (592 CTAs): dense pair-task loop, gate-free.
//  Warp pulls task-id (prefetched atomic), binary-search decode over the
//  192-entry prefix table -> (type, it, jt). Fixed-32 packed-f32x2 MUFU
//  loop (R12 machinery, R=4). Symmetry: sym types enumerate jt >= it*4;
//  strictly-upper tiles get x2 folded into the exponent (+1 in log2).
//  Last CTA finalizes and resets ALL state (incl. hist) for graph replay.
// ---------------------------------------------------------------------------
__global__ __launch_bounds__(THREADS, 4) void k_main(float* __restrict__ out) {
    __shared__ ull wtile[WPC][2][JTILE][4];
    __shared__ double sred[THREADS];
    __shared__ int s_pref[NENTRY + 1];
    __shared__ int s_js[NENTRY];
    __shared__ int s_last;

    const int tid  = threadIdx.x;
    const int wid  = tid >> 5;
    const int lane = tid & 31;

    // params from device state (delta) — inputs already folded into g_sb/g_st
    __shared__ float s_d[2];
    __shared__ float s_c2;
    if (tid < 2) s_d[tid] = g_delta[tid];
    if (tid == 0) s_last = 0;

    // recompute c2 from the sorted data? No — it depends only on log_sigma;
    // cheapest is recompute from a point-free identity: store via delta? We
    // recompute from the prefix-table inputs instead: pass through g_mean is
    // messy — simply recompute from the global arrays' generating params is
    // impossible here, so c2 comes from log_sigma directly:
    // (kernel arg-free path) -> read it from constant inputs via out? Keep it
    // simple: recompute in k_prep and stash in g_delta[2..3]? Instead we use
    // a dedicated global below.
    extern __device__ float g_c2m[2];
    if (tid == 0) s_c2 = 0.0f;  // placeholder (overwritten below)
    if (tid <= NENTRY) s_pref[tid] = g_prefix[tid];
    if (tid < NENTRY)  s_js[tid]   = g_jstart[tid];
    __syncthreads();

    const float c2 = g_c2m[0];
    const float m  = g_c2m[1];
    const float dx = s_d[0], dy = s_d[1];
    const int ntasks = s_pref[NENTRY];
    const unsigned int tbase =
        (unsigned int)__cvta_generic_to_shared(&wtile[wid][0][0][0]);

    double abb = 0.0, att = 0.0, abt = 0.0;
    unsigned int buf = 0u;

    unsigned int tnext = 0u;
    if (lane == 0) tnext = atomicAdd(&g_task, 1u);
    int t = (int)__shfl_sync(FULLMASK, tnext, 0);

    while (t < ntasks) {
        if (lane == 0) tnext = atomicAdd(&g_task, 1u);

        // decode: binary search prefix (warp-uniform, smem)
        int lo = 0, hi = NENTRY - 1;
        while (lo < hi) {
            int mid = (lo + hi + 1) >> 1;
            if (s_pref[mid] <= t) lo = mid; else hi = mid - 1;
        }
        const int e = lo;
        const int type = e >> 6;
        const int it = e & (IBLKS - 1);
        const int jt = s_js[e] + (t - s_pref[e]);
        const float wadd = (type < 2 && jt >= (it + 1) * JPB) ? 1.0f : 0.0f;

        const float2* __restrict__ Ai = (type == 1) ? g_st : g_sb;
        const float2* __restrict__ Bj = (type == 0) ? g_sb : g_st;
        const float jdx = (type == 2) ? dx : 0.0f;
        const float jdy = (type == 2) ? dy : 0.0f;

        // warp-private j-tile, double-buffered: (u,u)(v,v)(a,a)
        {
            float2 q = Bj[jt * JTILE + lane];
            float x = q.x + jdx;
            float y = q.y + jdy;
            float a = c2 * fmaf(x, x, y * y) + wadd;
            ull uu = pack2(m * x, m * x);
            ull vv = pack2(m * y, m * y);
            ull aa = pack2(a, a);
            unsigned int ta = tbase + buf * (JTILE * 32) + lane * 32;
            asm volatile("st.shared.v2.u64 [%0], {%1, %2};"
                         :: "r"(ta), "l"(uu), "l"(vv));
            asm volatile("st.shared.u64 [%0+16], %1;"
                         :: "r"(ta), "l"(aa));
        }

        // i-side, packed f32x2 (R=4 -> 2 chains)
        ull xii[NC], yii[NC], aii[NC];
        int i0 = it * ICHUNK + lane;
#pragma unroll
        for (int c = 0; c < NC; c++) {
            float2 p0 = Ai[i0 + (2 * c)     * 32];
            float2 p1 = Ai[i0 + (2 * c + 1) * 32];
            float a0 = c2 * fmaf(p0.x, p0.x, p0.y * p0.y);
            float a1 = c2 * fmaf(p1.x, p1.x, p1.y * p1.y);
            xii[c] = pack2(p0.x, p1.x);
            yii[c] = pack2(p0.y, p1.y);
            aii[c] = pack2(a0, a1);
        }

        __syncwarp();

        float acc[R];
#pragma unroll
        for (int r = 0; r < R; r++) acc[r] = 0.0f;

        unsigned int taddr = tbase + buf * (JTILE * 32);
#pragma unroll 4
        for (int j = 0; j < JTILE; j++) {
            ull uu, vv, aa;
            asm("ld.shared.v2.u64 {%0, %1}, [%2];"
                : "=l"(uu), "=l"(vv) : "r"(taddr));
            asm("ld.shared.u64 %0, [%1+16];"
                : "=l"(aa) : "r"(taddr));
            taddr += 32;
#pragma unroll
            for (int c = 0; c < NC; c++) {
                ull arg;
                asm("add.rn.f32x2 %0, %1, %2;"
                    : "=l"(arg) : "l"(aii[c]), "l"(aa));
                asm("fma.rn.f32x2 %0, %1, %2, %3;"
                    : "=l"(arg) : "l"(yii[c]), "l"(vv), "l"(arg));
                asm("fma.rn.f32x2 %0, %1, %2, %3;"
                    : "=l"(arg) : "l"(xii[c]), "l"(uu), "l"(arg));
                float flo, fhi;
                asm("mov.b64 {%0, %1}, %2;" : "=f"(flo), "=f"(fhi) : "l"(arg));
                acc[2 * c]     += ex2_approx(flo);
                acc[2 * c + 1] += ex2_approx(fhi);
            }
        }

        float s = (acc[0] + acc[1]) + (acc[2] + acc[3]);
        if      (type == 0) abb += (double)s;
        else if (type == 1) att += (double)s;
        else                abt += (double)s;

        buf ^= 1u;
        t = (int)__shfl_sync(FULLMASK, tnext, 0);
    }

    // ---- CTA reduction + atomics ----
    __syncthreads();
    block_reduce_add(abb, &g_sum[0], sred, tid);
    block_reduce_add(att, &g_sum[1], sred, tid);
    block_reduce_add(abt, &g_sum[2], sred, tid);

    // ---- finalize + full state reset (last CTA, block-parallel) ----
    if (tid == 0) {
        __threadfence();
        unsigned int d = atomicAdd(&g_done, 1u);
        if (d == (unsigned int)(GRID - 1)) s_last = 1;
    }
    __syncthreads();
    if (s_last) {
        // re-zero histograms for the next graph replay (block-parallel)
        for (int k = tid; k < NBIN; k += THREADS) {
            g_histb[k] = 0u;
            g_histt[k] = 0u;
        }
        if (tid == 0) {
            double sbb = atomicAdd(&g_sum[0], 0.0);
            double stt = atomicAdd(&g_sum[1], 0.0);
            double sbt = atomicAdd(&g_sum[2], 0.0);
            double inv = 1.0 / ((double)NPTS * (double)NPTS);
            out[0] = (float)((sbb + stt - 2.0 * sbt) * inv);
            g_sum[0] = 0.0; g_sum[1] = 0.0; g_sum[2] = 0.0;
            g_mean[0] = 0.0; g_mean[1] = 0.0;
            g_task = 0u; g_done = 0u;
            g_barB = 0u; g_barE = 0u; g_barDel = 0u; g_flagC = 0u;
            __threadfence();
        }
    }
}

// stash for (c2, m) computed in a tiny param kernel (avoids reloading
// log_sigma in k_main)
__device__ float g_c2m[2];

__global__ void k_params(const float* __restrict__ log_sigma) {
    float sigma = expf(log_sigma[0]);
    float c2 = -(1.0f / (2.0f * sigma * sigma)) * LOG2E_F;
    g_c2m[0] = c2;
    g_c2m[1] = -2.0f * c2;
}

// ---------------------------------------------------------------------------
extern "C" void kernel_launch(void* const* d_in, const int* in_sizes, int n_in,
                              void* d_out, int out_size) {
    const float* base = (const float*)d_in[0];
    const float* tgt  = (const float*)d_in[1];
    const float* lsig = (const float*)d_in[2];
    const float* lsc  = (const float*)d_in[3];

    k_params<<<1, 1>>>(lsig);
    k_prep<<<PREP_CTAS, THREADS>>>(base, tgt, lsig, lsc);
    k_main<<<GRID, THREADS>>>((float*)d_out);
}